// round 14
// baseline (speedup 1.0000x reference)
#include <cuda_runtime.h>
#include <cuda_fp16.h>
#include <cstdint>

#define FF 128
#define HH 512
#define HH2 256   // half2 per row
#define MAXN 50048
#define MAXE 401408
#define SCAN_B 1024

// Scratch (static device globals — no runtime allocation allowed)
__device__ __align__(16) uint32_t g_h[(size_t)50000 * HH2];  // h' rows fp16 (half2)
__device__ __align__(16) uint32_t g_wh[512 * 64];            // W fp16 (half2), [512][64]
__device__ int   g_cnt[MAXN];
__device__ float g_dinv[MAXN];
__device__ int   g_rowptr[MAXN + 1];
__device__ int   g_cur[MAXN];
__device__ int   g_srcidx[MAXE];
__device__ volatile int g_bval[64];
__device__ volatile int g_bflag[64];

// ---------------------------------------------------------------------------
// count (edge targets) + W->fp16 prep + lookback-flag reset, fused
// ---------------------------------------------------------------------------
__global__ void count_wprep_kernel(const int* __restrict__ ei,
                                   const float* __restrict__ W,
                                   int E, int n, int countBlocks) {
    int bid = blockIdx.x;
    if (bid == 0 && threadIdx.x < 64) {
        g_bflag[threadIdx.x] = 0;
        g_bval[threadIdx.x]  = 0;
    }
    if (bid < countBlocks) {
        int e = bid * 256 + threadIdx.x;
        if (e < E) {
            int c = ei[E + e];
            if ((unsigned)c < (unsigned)n) atomicAdd(&g_cnt[c], 1);
        }
    } else {
        int i = (bid - countBlocks) * 256 + threadIdx.x;
        if (i < 512 * 64) {
            float2 v = ((const float2*)W)[i];
            __half2 h = __floats2half2_rn(v.x, v.y);
            g_wh[i] = *(uint32_t*)&h;
        }
    }
}

// Fused scan: per-block scan + decoupled lookback + dinv + cnt re-zero
__global__ void scan_fused_kernel(int n, int E) {
    __shared__ int sh[SCAN_B];
    __shared__ int exc;
    int bid = blockIdx.x;
    int gid = bid * SCAN_B + threadIdx.x;
    int v = 0;
    if (gid < n) {
        v = g_cnt[gid];
        g_cnt[gid] = 0;
        g_dinv[gid] = rsqrtf((float)(v + 1));
    }
    sh[threadIdx.x] = v;
    __syncthreads();
#pragma unroll
    for (int off = 1; off < SCAN_B; off <<= 1) {
        int t = (threadIdx.x >= off) ? sh[threadIdx.x - off] : 0;
        __syncthreads();
        sh[threadIdx.x] += t;
        __syncthreads();
    }
    if (threadIdx.x == 0) {
        g_bval[bid] = sh[SCAN_B - 1];
        __threadfence();
        g_bflag[bid] = 1;
        int sum = 0;
        for (int j = bid - 1; j >= 0; j--) {
            while (g_bflag[j] == 0) { }
            sum += g_bval[j];
        }
        exc = sum;
    }
    __syncthreads();
    if (gid < n) {
        int val = sh[threadIdx.x] - v + exc;
        g_rowptr[gid] = val;
        g_cur[gid] = val;
    }
    if (gid == 0) g_rowptr[n] = E;
}

__global__ void fill_kernel(const int* __restrict__ ei, int E, int n) {
    int e = blockIdx.x * blockDim.x + threadIdx.x;
    if (e < E) {
        int r = ei[e];
        int c = ei[E + e];
        if ((unsigned)r < (unsigned)n && (unsigned)c < (unsigned)n) {
            int pos = atomicAdd(&g_cur[c], 1);
            g_srcidx[pos] = r;
        }
    }
}

// ---------------------------------------------------------------------------
// fp16 tensor-core GEMM (m16n8k16), single-stage: full 128x128x128 tile in
// smem, ONE barrier, then an uninterrupted ldsm+mma stream (no pipeline).
//   As: [128][68] half2  34816 B ; Bs: [128][68] half2  34816 B  -> 69632 B
// Grid: (4 N-tiles, ceil(M/128)).
// ---------------------------------------------------------------------------
#define AS_LDH 68
#define AS_BYTESH (128 * AS_LDH * 4)
#define SMEM_TOTAL_GEMM (2 * AS_BYTESH)   // 69632

__device__ __forceinline__ void mma16(float* c, const uint32_t* a,
                                      uint32_t b0, uint32_t b1) {
    asm volatile(
        "mma.sync.aligned.m16n8k16.row.col.f32.f16.f16.f32 "
        "{%0,%1,%2,%3}, {%4,%5,%6,%7}, {%8,%9}, {%0,%1,%2,%3};"
        : "+f"(c[0]), "+f"(c[1]), "+f"(c[2]), "+f"(c[3])
        : "r"(a[0]), "r"(a[1]), "r"(a[2]), "r"(a[3]), "r"(b0), "r"(b1));
}

__device__ __forceinline__ void ldsm_x4(uint32_t& r0, uint32_t& r1,
                                        uint32_t& r2, uint32_t& r3,
                                        uint32_t saddr) {
    asm volatile("ldmatrix.sync.aligned.m8n8.x4.shared.b16 {%0,%1,%2,%3}, [%4];"
                 : "=r"(r0), "=r"(r1), "=r"(r2), "=r"(r3) : "r"(saddr));
}

__device__ __forceinline__ void cp_async16(void* sptr, const void* gptr) {
    uint32_t sa = (uint32_t)__cvta_generic_to_shared(sptr);
    asm volatile("cp.async.cg.shared.global [%0], [%1], 16;" :: "r"(sa), "l"(gptr));
}
__device__ __forceinline__ void cp_commit() {
    asm volatile("cp.async.commit_group;");
}
template <int NN>
__device__ __forceinline__ void cp_wait() {
    asm volatile("cp.async.wait_group %0;" :: "n"(NN));
}

__global__ __launch_bounds__(256) void fp16_gemm_kernel(
        const float* __restrict__ X, int M) {
    extern __shared__ char smem_raw[];
    uint32_t (*As)[AS_LDH] = (uint32_t(*)[AS_LDH])smem_raw;
    uint32_t (*Bs)[AS_LDH] = (uint32_t(*)[AS_LDH])(smem_raw + AS_BYTESH);

    const int t    = threadIdx.x;
    const int wid  = t >> 5;
    const int lane = t & 31;
    const int warp_m = wid & 3;    // 4 warps along M (32 rows each)
    const int warp_n = wid >> 2;   // 2 warps along N (64 cols each)
    const int nt = blockIdx.x;     // N tile (128 cols)
    const int bm = blockIdx.y * 128;
    const int fr = lane >> 2;
    const int fc = lane & 3;

    const uint32_t as_base = (uint32_t)__cvta_generic_to_shared(&As[0][0]);
    const uint32_t bs_base = (uint32_t)__cvta_generic_to_shared(&Bs[0][0]);

    // ---- B tile: 128 cols x full K, cp.async from fp16 g_wh ----
    // 128 rows x 64 half2 = 2048 x 16B chunks, 8 per thread.
#pragma unroll
    for (int i = 0; i < 8; i++) {
        int idx = t + i * 256;
        int row = idx >> 4;           // 0..127
        int c16 = idx & 15;           // 16B chunk in row
        cp_async16(&Bs[row][c16 * 4],
                   &g_wh[(size_t)(nt * 128 + row) * 64 + c16 * 4]);
    }
    cp_commit();

    // ---- A tile: 128 rows x full K, fp32 LDG -> fp16 half2 STS ----
#pragma unroll
    for (int i = 0; i < 16; i++) {
        int idx = t + i * 256;
        int row = idx >> 5;
        int c4  = idx & 31;
        int gm  = bm + row;
        float4 v = make_float4(0.f, 0.f, 0.f, 0.f);
        if (gm < M) v = *(const float4*)&X[(size_t)gm * FF + c4 * 4];
        __half2 h0 = __floats2half2_rn(v.x, v.y);
        __half2 h1 = __floats2half2_rn(v.z, v.w);
        As[row][c4 * 2]     = *(uint32_t*)&h0;
        As[row][c4 * 2 + 1] = *(uint32_t*)&h1;
    }

    cp_wait<0>();
    __syncthreads();          // the ONLY barrier before the epilogue

    float c[2][8][4];
#pragma unroll
    for (int mt = 0; mt < 2; mt++)
#pragma unroll
        for (int j = 0; j < 8; j++)
#pragma unroll
            for (int q = 0; q < 4; q++) c[mt][j][q] = 0.f;

    const int a_row = warp_m * 32 + (lane & 15);
    const int a_col = (lane >> 4) * 4;            // + kk*8 (half2)
    const int b_jj  = (lane >> 4);
    const int b_row = warp_n * 64 + (lane & 7);
    const int b_col = ((lane >> 3) & 1) * 4;      // + kk*8 (half2)

    // 8 uninterrupted k16 steps, no barriers
#pragma unroll
    for (int kk = 0; kk < 8; kk++) {
        uint32_t a[2][4];
#pragma unroll
        for (int mt = 0; mt < 2; mt++) {
            uint32_t addr = as_base +
                (uint32_t)(((a_row + mt * 16) * AS_LDH) + kk * 8 + a_col) * 4;
            ldsm_x4(a[mt][0], a[mt][1], a[mt][2], a[mt][3], addr);
        }
#pragma unroll
        for (int j = 0; j < 8; j += 2) {
            uint32_t addr = bs_base +
                (uint32_t)(((b_row + (j + b_jj) * 8) * AS_LDH) + kk * 8 + b_col) * 4;
            uint32_t b0, b1, b2, b3;
            ldsm_x4(b0, b1, b2, b3, addr);
            mma16(c[0][j],     a[0], b0, b1);
            mma16(c[1][j],     a[1], b0, b1);
            mma16(c[0][j + 1], a[0], b2, b3);
            mma16(c[1][j + 1], a[1], b2, b3);
        }
    }

    // Epilogue: scale by dinv[row], fp16 stores
#pragma unroll
    for (int mt = 0; mt < 2; mt++) {
        int r0 = bm + warp_m * 32 + mt * 16 + fr;
        int r1 = r0 + 8;
        float s0 = (r0 < M) ? g_dinv[r0] : 0.f;
        float s1 = (r1 < M) ? g_dinv[r1] : 0.f;
#pragma unroll
        for (int j = 0; j < 8; j++) {
            int colh = nt * 64 + warp_n * 32 + j * 4 + fc;
            if (r0 < M) {
                __half2 h = __floats2half2_rn(c[mt][j][0] * s0, c[mt][j][1] * s0);
                g_h[(size_t)r0 * HH2 + colh] = *(uint32_t*)&h;
            }
            if (r1 < M) {
                __half2 h = __floats2half2_rn(c[mt][j][2] * s1, c[mt][j][3] * s1);
                g_h[(size_t)r1 * HH2 + colh] = *(uint32_t*)&h;
            }
        }
    }
}

// ---------------------------------------------------------------------------
// Pull + finalize fused: one warp per node; fp16 gather (4-edge unroll),
// fp32 accumulate; streaming out stores.
// ---------------------------------------------------------------------------
__device__ __forceinline__ void acc_uint4(float2* acc, uint4 v) {
    float2 f;
    f = __half22float2(*(__half2*)&v.x); acc[0].x += f.x; acc[0].y += f.y;
    f = __half22float2(*(__half2*)&v.y); acc[1].x += f.x; acc[1].y += f.y;
    f = __half22float2(*(__half2*)&v.z); acc[2].x += f.x; acc[2].y += f.y;
    f = __half22float2(*(__half2*)&v.w); acc[3].x += f.x; acc[3].y += f.y;
}

__global__ void pull_kernel(float* __restrict__ out,
                            const float* __restrict__ b,
                            const float* __restrict__ alpha,
                            int n) {
    int warp = (blockIdx.x * blockDim.x + threadIdx.x) >> 5;
    int lane = threadIdx.x & 31;
    if (warp >= n) return;
    int node = warp;
    int beg = g_rowptr[node];
    int end = g_rowptr[node + 1];

    const uint4* self = (const uint4*)&g_h[(size_t)node * HH2];
    float2 acc[2][4];
#pragma unroll
    for (int i = 0; i < 2; i++) {
        uint4 v = self[lane + i * 32];
        acc[i][0] = __half22float2(*(__half2*)&v.x);
        acc[i][1] = __half22float2(*(__half2*)&v.y);
        acc[i][2] = __half22float2(*(__half2*)&v.z);
        acc[i][3] = __half22float2(*(__half2*)&v.w);
    }

    int e = beg;
    for (; e + 3 < end; e += 4) {
        int r0 = g_srcidx[e];
        int r1 = g_srcidx[e + 1];
        int r2 = g_srcidx[e + 2];
        int r3 = g_srcidx[e + 3];
        const uint4* s0 = (const uint4*)&g_h[(size_t)r0 * HH2];
        const uint4* s1 = (const uint4*)&g_h[(size_t)r1 * HH2];
        const uint4* s2 = (const uint4*)&g_h[(size_t)r2 * HH2];
        const uint4* s3 = (const uint4*)&g_h[(size_t)r3 * HH2];
        uint4 v00 = s0[lane], v01 = s0[lane + 32];
        uint4 v10 = s1[lane], v11 = s1[lane + 32];
        uint4 v20 = s2[lane], v21 = s2[lane + 32];
        uint4 v30 = s3[lane], v31 = s3[lane + 32];
        acc_uint4(acc[0], v00); acc_uint4(acc[1], v01);
        acc_uint4(acc[0], v10); acc_uint4(acc[1], v11);
        acc_uint4(acc[0], v20); acc_uint4(acc[1], v21);
        acc_uint4(acc[0], v30); acc_uint4(acc[1], v31);
    }
    for (; e < end; e++) {
        int r0 = g_srcidx[e];
        const uint4* s0 = (const uint4*)&g_h[(size_t)r0 * HH2];
        acc_uint4(acc[0], s0[lane]);
        acc_uint4(acc[1], s0[lane + 32]);
    }

    float s = g_dinv[node];
    float* dst = &out[(size_t)node * HH];
#pragma unroll
    for (int i = 0; i < 2; i++) {
#pragma unroll
        for (int j = 0; j < 4; j += 2) {
            int colh = (lane + i * 32) * 4 + j;
            float4 bb = *(const float4*)&((const float2*)b)[colh];
            float4 aa = *(const float4*)&((const float2*)alpha)[colh];
            float2 v0 = acc[i][j];
            float2 v1 = acc[i][j + 1];
            float4 r;
            r.x = v0.x * s + bb.x;  r.x = r.x > 0.f ? r.x : aa.x * r.x;
            r.y = v0.y * s + bb.y;  r.y = r.y > 0.f ? r.y : aa.y * r.y;
            r.z = v1.x * s + bb.z;  r.z = r.z > 0.f ? r.z : aa.z * r.z;
            r.w = v1.y * s + bb.w;  r.w = r.w > 0.f ? r.w : aa.w * r.w;
            __stcs((float4*)&((float2*)dst)[colh], r);
        }
    }
}

// ---------------------------------------------------------------------------
// Launch
// ---------------------------------------------------------------------------
extern "C" void kernel_launch(void* const* d_in, const int* in_sizes, int n_in,
                              void* d_out, int out_size) {
    const float* x     = (const float*)d_in[0];  // [N, 128]
    const int*   ei    = (const int*)d_in[1];    // [2, E] int32
    const float* W     = (const float*)d_in[2];  // [512, 128]
    const float* b     = (const float*)d_in[3];  // [512]
    const float* alpha = (const float*)d_in[4];  // [512]
    float*       out   = (float*)d_out;          // [N, 512]

    const int N = in_sizes[0] / FF;
    const int E = in_sizes[1] / 2;
    const int nb = (N + SCAN_B - 1) / SCAN_B;
    const int countBlocks = (E + 255) / 256;
    const int wprepBlocks = (512 * 64 + 255) / 256;

    cudaFuncSetAttribute(fp16_gemm_kernel,
                         cudaFuncAttributeMaxDynamicSharedMemorySize,
                         SMEM_TOTAL_GEMM);

    // 1) count + W->fp16 + flag reset, fused
    count_wprep_kernel<<<countBlocks + wprepBlocks, 256>>>(ei, W, E, N, countBlocks);
    // 2) fused scan (dinv, cnt re-zero, rowptr, cur)
    scan_fused_kernel<<<nb, SCAN_B>>>(N, E);
    // 3) CSR fill
    fill_kernel<<<(E + 255) / 256, 256>>>(ei, E, N);

    // 4) g_h = fp16((x @ W^T) * dinv[row]) — single-stage tile, 1 barrier
    dim3 gemm_grid(4, (N + 127) / 128);
    fp16_gemm_kernel<<<gemm_grid, 256, SMEM_TOTAL_GEMM>>>(x, N);

    // 5) pull-based aggregate + finalize
    int warps_per_block = 256 / 32;
    pull_kernel<<<(N + warps_per_block - 1) / warps_per_block, 256>>>(out, b, alpha, N);
}

// round 15
// speedup vs baseline: 1.2924x; 1.2924x over previous
#include <cuda_runtime.h>
#include <cuda_fp16.h>
#include <cstdint>

#define FF 128
#define HH 512
#define MAXN 50048
#define MAXE 401408
#define SCAN_B 1024

// Scratch (static device globals — no runtime allocation allowed)
__device__ __align__(16) uint32_t g_agg[(size_t)50000 * 64]; // agg rows fp16 (64 half2)
__device__ __align__(16) uint32_t g_wh[512 * 64];            // W fp16 (half2), [512][64]
__device__ int   g_cnt[MAXN];
__device__ float g_dinv[MAXN];
__device__ int   g_rowptr[MAXN + 1];
__device__ int   g_cur[MAXN];
__device__ int   g_srcidx[MAXE];
__device__ volatile int g_bval[64];
__device__ volatile int g_bflag[64];

// ---------------------------------------------------------------------------
// count (edge targets) + W->fp16 prep + lookback-flag reset, fused
// ---------------------------------------------------------------------------
__global__ void count_wprep_kernel(const int* __restrict__ ei,
                                   const float* __restrict__ W,
                                   int E, int n, int countBlocks) {
    int bid = blockIdx.x;
    if (bid == 0 && threadIdx.x < 64) {
        g_bflag[threadIdx.x] = 0;
        g_bval[threadIdx.x]  = 0;
    }
    if (bid < countBlocks) {
        int e = bid * 256 + threadIdx.x;
        if (e < E) {
            int c = ei[E + e];
            if ((unsigned)c < (unsigned)n) atomicAdd(&g_cnt[c], 1);
        }
    } else {
        int i = (bid - countBlocks) * 256 + threadIdx.x;
        if (i < 512 * 64) {
            float2 v = ((const float2*)W)[i];
            __half2 h = __floats2half2_rn(v.x, v.y);
            g_wh[i] = *(uint32_t*)&h;
        }
    }
}

// Fused scan: per-block scan + decoupled lookback + dinv + cnt re-zero
__global__ void scan_fused_kernel(int n, int E) {
    __shared__ int sh[SCAN_B];
    __shared__ int exc;
    int bid = blockIdx.x;
    int gid = bid * SCAN_B + threadIdx.x;
    int v = 0;
    if (gid < n) {
        v = g_cnt[gid];
        g_cnt[gid] = 0;
        g_dinv[gid] = rsqrtf((float)(v + 1));
    }
    sh[threadIdx.x] = v;
    __syncthreads();
#pragma unroll
    for (int off = 1; off < SCAN_B; off <<= 1) {
        int t = (threadIdx.x >= off) ? sh[threadIdx.x - off] : 0;
        __syncthreads();
        sh[threadIdx.x] += t;
        __syncthreads();
    }
    if (threadIdx.x == 0) {
        g_bval[bid] = sh[SCAN_B - 1];
        __threadfence();
        g_bflag[bid] = 1;
        int sum = 0;
        for (int j = bid - 1; j >= 0; j--) {
            while (g_bflag[j] == 0) { }
            sum += g_bval[j];
        }
        exc = sum;
    }
    __syncthreads();
    if (gid < n) {
        int val = sh[threadIdx.x] - v + exc;
        g_rowptr[gid] = val;
        g_cur[gid] = val;
    }
    if (gid == 0) g_rowptr[n] = E;
}

__global__ void fill_kernel(const int* __restrict__ ei, int E, int n) {
    int e = blockIdx.x * blockDim.x + threadIdx.x;
    if (e < E) {
        int r = ei[e];
        int c = ei[E + e];
        if ((unsigned)r < (unsigned)n && (unsigned)c < (unsigned)n) {
            int pos = atomicAdd(&g_cur[c], 1);
            g_srcidx[pos] = r;
        }
    }
}

// ---------------------------------------------------------------------------
// pull_x: aggregate RAW X rows (commuted GCN). One warp per node, lane holds
// one float4 (16B x 32 = 512B row). agg[c] = fp16(dinv[c]*(dinv[c]*x[c] +
// sum_r dinv[r]*x[r])).
// ---------------------------------------------------------------------------
__global__ void pull_x_kernel(const float* __restrict__ x, int n) {
    int warp = (blockIdx.x * blockDim.x + threadIdx.x) >> 5;
    int lane = threadIdx.x & 31;
    if (warp >= n) return;
    int node = warp;
    int beg = g_rowptr[node];
    int end = g_rowptr[node + 1];

    float s = g_dinv[node];
    float4 v = __ldg(&((const float4*)&x[(size_t)node * FF])[lane]);
    float4 acc = make_float4(v.x * s, v.y * s, v.z * s, v.w * s);

    int e = beg;
    for (; e + 3 < end; e += 4) {
        int r0 = g_srcidx[e];
        int r1 = g_srcidx[e + 1];
        int r2 = g_srcidx[e + 2];
        int r3 = g_srcidx[e + 3];
        float d0 = g_dinv[r0], d1 = g_dinv[r1], d2 = g_dinv[r2], d3 = g_dinv[r3];
        float4 v0 = __ldg(&((const float4*)&x[(size_t)r0 * FF])[lane]);
        float4 v1 = __ldg(&((const float4*)&x[(size_t)r1 * FF])[lane]);
        float4 v2 = __ldg(&((const float4*)&x[(size_t)r2 * FF])[lane]);
        float4 v3 = __ldg(&((const float4*)&x[(size_t)r3 * FF])[lane]);
        acc.x += v0.x * d0 + v1.x * d1 + v2.x * d2 + v3.x * d3;
        acc.y += v0.y * d0 + v1.y * d1 + v2.y * d2 + v3.y * d3;
        acc.z += v0.z * d0 + v1.z * d1 + v2.z * d2 + v3.z * d3;
        acc.w += v0.w * d0 + v1.w * d1 + v2.w * d2 + v3.w * d3;
    }
    for (; e < end; e++) {
        int r0 = g_srcidx[e];
        float d0 = g_dinv[r0];
        float4 v0 = __ldg(&((const float4*)&x[(size_t)r0 * FF])[lane]);
        acc.x += v0.x * d0; acc.y += v0.y * d0;
        acc.z += v0.z * d0; acc.w += v0.w * d0;
    }

    acc.x *= s; acc.y *= s; acc.z *= s; acc.w *= s;
    __half2 h0 = __floats2half2_rn(acc.x, acc.y);
    __half2 h1 = __floats2half2_rn(acc.z, acc.w);
    g_agg[(size_t)node * 64 + lane * 2]     = *(uint32_t*)&h0;
    g_agg[(size_t)node * 64 + lane * 2 + 1] = *(uint32_t*)&h1;
}

// ---------------------------------------------------------------------------
// fp16 tensor-core GEMM (m16n8k16), A-resident (agg, fp16 cp.async) +
// cp.async double-buffered B; fused +b / PReLU epilogue -> out (fp32, stcs).
//   As: [128][68] half2  34816 B ; Bs: [2][128][20] half2  20480 B
// ---------------------------------------------------------------------------
#define AS_LDH 68
#define BS_LDH 20
#define AS_BYTESH (128 * AS_LDH * 4)
#define BS_BYTESH (2 * 128 * BS_LDH * 4)
#define SMEM_TOTAL_GEMM (AS_BYTESH + BS_BYTESH)   // 55296

__device__ __forceinline__ void mma16(float* c, const uint32_t* a,
                                      uint32_t b0, uint32_t b1) {
    asm volatile(
        "mma.sync.aligned.m16n8k16.row.col.f32.f16.f16.f32 "
        "{%0,%1,%2,%3}, {%4,%5,%6,%7}, {%8,%9}, {%0,%1,%2,%3};"
        : "+f"(c[0]), "+f"(c[1]), "+f"(c[2]), "+f"(c[3])
        : "r"(a[0]), "r"(a[1]), "r"(a[2]), "r"(a[3]), "r"(b0), "r"(b1));
}

__device__ __forceinline__ void ldsm_x4(uint32_t& r0, uint32_t& r1,
                                        uint32_t& r2, uint32_t& r3,
                                        uint32_t saddr) {
    asm volatile("ldmatrix.sync.aligned.m8n8.x4.shared.b16 {%0,%1,%2,%3}, [%4];"
                 : "=r"(r0), "=r"(r1), "=r"(r2), "=r"(r3) : "r"(saddr));
}

__device__ __forceinline__ void cp_async16(void* sptr, const void* gptr) {
    uint32_t sa = (uint32_t)__cvta_generic_to_shared(sptr);
    asm volatile("cp.async.cg.shared.global [%0], [%1], 16;" :: "r"(sa), "l"(gptr));
}
__device__ __forceinline__ void cp_commit() {
    asm volatile("cp.async.commit_group;");
}
template <int NN>
__device__ __forceinline__ void cp_wait() {
    asm volatile("cp.async.wait_group %0;" :: "n"(NN));
}

__global__ __launch_bounds__(256) void gemm_out_kernel(
        float* __restrict__ out,
        const float* __restrict__ b,
        const float* __restrict__ alpha,
        int M) {
    extern __shared__ char smem_raw[];
    uint32_t (*As)[AS_LDH]      = (uint32_t(*)[AS_LDH])smem_raw;
    uint32_t (*Bs)[128][BS_LDH] = (uint32_t(*)[128][BS_LDH])(smem_raw + AS_BYTESH);

    const int t    = threadIdx.x;
    const int wid  = t >> 5;
    const int lane = t & 31;
    const int warp_m = wid & 3;
    const int warp_n = wid >> 2;
    const int bm = blockIdx.x * 128;
    const int fr = lane >> 2;
    const int fc = lane & 3;

    const uint32_t as_base = (uint32_t)__cvta_generic_to_shared(&As[0][0]);
    const uint32_t bs_base = (uint32_t)__cvta_generic_to_shared(&Bs[0][0][0]);

    // ---- A tile: agg rows (already fp16), pure cp.async ----
    // 128 rows x 16 chunks(16B) = 2048 chunks, 8 per thread.
#pragma unroll
    for (int i = 0; i < 8; i++) {
        int idx = t + i * 256;
        int row = idx >> 4;
        int c16 = idx & 15;
        int gm = bm + row; if (gm >= M) gm = M - 1;   // clamp; tail rows unused
        cp_async16(&As[row][c16 * 4], &g_agg[(size_t)gm * 64 + c16 * 4]);
    }
    cp_commit();

    auto issueB = [&](int s, int buf) {
        int nt = s >> 2, kt = s & 3;
#pragma unroll
        for (int i = 0; i < 2; i++) {
            int idx = t + i * 256;
            int row = idx >> 2;
            int c16 = idx & 3;
            cp_async16(&Bs[buf][row][c16 * 4],
                       &g_wh[(size_t)(nt * 128 + row) * 64 + kt * 16 + c16 * 4]);
        }
        cp_commit();
    };

    issueB(0, 0);

    float c[2][8][4];
#pragma unroll
    for (int mt = 0; mt < 2; mt++)
#pragma unroll
        for (int j = 0; j < 8; j++)
#pragma unroll
            for (int q = 0; q < 4; q++) c[mt][j][q] = 0.f;

    const int a_row = warp_m * 32 + (lane & 15);
    const int a_col = (lane >> 4) * 4;
    const int b_jj  = (lane >> 4);
    const int b_row = warp_n * 64 + (lane & 7);
    const int b_col = ((lane >> 3) & 1) * 4;

    for (int s = 0; s < 16; s++) {
        int buf = s & 1;
        if (s < 15) { issueB(s + 1, buf ^ 1); cp_wait<1>(); }
        else        { cp_wait<0>(); }
        __syncthreads();

        const int kt = s & 3;
#pragma unroll
        for (int ks = 0; ks < 2; ks++) {
            uint32_t a[2][4];
#pragma unroll
            for (int mt = 0; mt < 2; mt++) {
                uint32_t addr = as_base +
                    (uint32_t)(((a_row + mt * 16) * AS_LDH) + kt * 16 + ks * 8 + a_col) * 4;
                ldsm_x4(a[mt][0], a[mt][1], a[mt][2], a[mt][3], addr);
            }
#pragma unroll
            for (int j = 0; j < 8; j += 2) {
                uint32_t addr = bs_base + (uint32_t)buf * (128 * BS_LDH * 4) +
                    (uint32_t)(((b_row + (j + b_jj) * 8) * BS_LDH) + ks * 8 + b_col) * 4;
                uint32_t b0, b1, b2, b3;
                ldsm_x4(b0, b1, b2, b3, addr);
                mma16(c[0][j],     a[0], b0, b1);
                mma16(c[1][j],     a[1], b0, b1);
                mma16(c[0][j + 1], a[0], b2, b3);
                mma16(c[1][j + 1], a[1], b2, b3);
            }
        }
        __syncthreads();

        if ((s & 3) == 3) {
            // epilogue for this 128-col N block: +b, PReLU, fp32 stcs to out
            int nt = s >> 2;
#pragma unroll
            for (int mt = 0; mt < 2; mt++) {
                int r0 = bm + warp_m * 32 + mt * 16 + fr;
                int r1 = r0 + 8;
#pragma unroll
                for (int j = 0; j < 8; j++) {
                    int col2 = nt * 64 + warp_n * 32 + j * 4 + fc;  // float2 col
                    float2 bb = __ldg(&((const float2*)b)[col2]);
                    float2 aa = __ldg(&((const float2*)alpha)[col2]);
                    if (r0 < M) {
                        float vx = c[mt][j][0] + bb.x; vx = vx > 0.f ? vx : aa.x * vx;
                        float vy = c[mt][j][1] + bb.y; vy = vy > 0.f ? vy : aa.y * vy;
                        __stcs(&((float2*)out)[(size_t)r0 * 256 + col2],
                               make_float2(vx, vy));
                    }
                    if (r1 < M) {
                        float vx = c[mt][j][2] + bb.x; vx = vx > 0.f ? vx : aa.x * vx;
                        float vy = c[mt][j][3] + bb.y; vy = vy > 0.f ? vy : aa.y * vy;
                        __stcs(&((float2*)out)[(size_t)r1 * 256 + col2],
                               make_float2(vx, vy));
                    }
#pragma unroll
                    for (int q = 0; q < 4; q++) c[mt][j][q] = 0.f;
                }
            }
        }
    }
}

// ---------------------------------------------------------------------------
// Launch
// ---------------------------------------------------------------------------
extern "C" void kernel_launch(void* const* d_in, const int* in_sizes, int n_in,
                              void* d_out, int out_size) {
    const float* x     = (const float*)d_in[0];  // [N, 128]
    const int*   ei    = (const int*)d_in[1];    // [2, E] int32
    const float* W     = (const float*)d_in[2];  // [512, 128]
    const float* b     = (const float*)d_in[3];  // [512]
    const float* alpha = (const float*)d_in[4];  // [512]
    float*       out   = (float*)d_out;          // [N, 512]

    const int N = in_sizes[0] / FF;
    const int E = in_sizes[1] / 2;
    const int nb = (N + SCAN_B - 1) / SCAN_B;
    const int countBlocks = (E + 255) / 256;
    const int wprepBlocks = (512 * 64 + 255) / 256;

    cudaFuncSetAttribute(gemm_out_kernel,
                         cudaFuncAttributeMaxDynamicSharedMemorySize,
                         SMEM_TOTAL_GEMM);

    // 1) count + W->fp16 + flag reset, fused
    count_wprep_kernel<<<countBlocks + wprepBlocks, 256>>>(ei, W, E, N, countBlocks);
    // 2) fused scan (dinv, cnt re-zero, rowptr, cur)
    scan_fused_kernel<<<nb, SCAN_B>>>(N, E);
    // 3) CSR fill
    fill_kernel<<<(E + 255) / 256, 256>>>(ei, E, N);

    // 4) agg = fp16(dinv * A_hat * (dinv-scaled X))  — commuted aggregation
    int warps_per_block = 256 / 32;
    pull_x_kernel<<<(N + warps_per_block - 1) / warps_per_block, 256>>>(x, N);

    // 5) out = prelu(agg @ Wh^T + b) — fp16 TC GEMM, fused epilogue
    gemm_out_kernel<<<(N + 127) / 128, 256, SMEM_TOTAL_GEMM>>>(out, b, alpha, N);
}